// round 16
// baseline (speedup 1.0000x reference)
#include <cuda_runtime.h>

#define D     64
#define PD    68            // padded smem row stride: 16B-aligned rows, conflict-free LDS.128
#define NMAX  12288
#define FULL  0xffffffffu
#define CAPG  128           // per-row nonzero list capacity (mean ~25, 20+ sigma headroom)
#define GATB  128           // gather blocks (consumers)
#define HQKB  148           // hqk blocks
#define SCANB 448           // scan blocks (producers); 3584 warps, ~3.4 rows each
#define SCANW (SCANB * 8)

// Scratch (allocation-free contract: __device__ globals)
__device__ float g_h [NMAX * D];
__device__ float g_qm[NMAX * D];            // q with first component pre-negated
__device__ float g_k [NMAX * D];
__device__ int   g_cnt [NMAX];              // -1 = not ready; >=0 = published count
__device__ int2  g_list[(size_t)NMAX * CAPG];   // {col j, float bits of adj value}
__device__ int   g_done;                    // hqk completion counter
__device__ int   g_tick;                    // gather row ticket

// 4-rows-per-warp cooperative 64x64 matvec; weights as float4 from padded smem.
__device__ __forceinline__ void matvec4(const float* __restrict__ sW,
                                        const float v0[4], const float v1[4],
                                        float bb0, float bb1, int lane,
                                        float o0[4], float o1[4])
{
    const float4* r0 = (const float4*)(sW + lane * PD);
    const float4* r1 = (const float4*)(sW + (lane + 32) * PD);
    float a0[4], a1[4];
#pragma unroll
    for (int k = 0; k < 4; k++) { a0[k] = bb0; a1[k] = bb1; }
#pragma unroll
    for (int c4 = 0; c4 < 8; c4++) {
        float4 w0 = r0[c4], w1 = r1[c4];
#pragma unroll
        for (int k = 0; k < 4; k++) {
            float x0 = __shfl_sync(FULL, v0[k], 4 * c4 + 0);
            float x1 = __shfl_sync(FULL, v0[k], 4 * c4 + 1);
            float x2 = __shfl_sync(FULL, v0[k], 4 * c4 + 2);
            float x3 = __shfl_sync(FULL, v0[k], 4 * c4 + 3);
            a0[k] = fmaf(x0, w0.x, a0[k]); a1[k] = fmaf(x0, w1.x, a1[k]);
            a0[k] = fmaf(x1, w0.y, a0[k]); a1[k] = fmaf(x1, w1.y, a1[k]);
            a0[k] = fmaf(x2, w0.z, a0[k]); a1[k] = fmaf(x2, w1.z, a1[k]);
            a0[k] = fmaf(x3, w0.w, a0[k]); a1[k] = fmaf(x3, w1.w, a1[k]);
        }
    }
#pragma unroll
    for (int c4 = 8; c4 < 16; c4++) {
        float4 w0 = r0[c4], w1 = r1[c4];
#pragma unroll
        for (int k = 0; k < 4; k++) {
            float x0 = __shfl_sync(FULL, v1[k], 4 * (c4 - 8) + 0);
            float x1 = __shfl_sync(FULL, v1[k], 4 * (c4 - 8) + 1);
            float x2 = __shfl_sync(FULL, v1[k], 4 * (c4 - 8) + 2);
            float x3 = __shfl_sync(FULL, v1[k], 4 * (c4 - 8) + 3);
            a0[k] = fmaf(x0, w0.x, a0[k]); a1[k] = fmaf(x0, w1.x, a1[k]);
            a0[k] = fmaf(x1, w0.y, a0[k]); a1[k] = fmaf(x1, w1.y, a1[k]);
            a0[k] = fmaf(x2, w0.z, a0[k]); a1[k] = fmaf(x2, w1.z, a1[k]);
            a0[k] = fmaf(x3, w0.w, a0[k]); a1[k] = fmaf(x3, w1.w, a1[k]);
        }
    }
#pragma unroll
    for (int k = 0; k < 4; k++) { o0[k] = a0[k]; o1[k] = a1[k]; }
}

__device__ __forceinline__ void lorentzify(float& h0, float& h1, float escale, int lane)
{
    float t    = __shfl_sync(FULL, h0, 0);
    float time = escale / (1.0f + __expf(-t)) + 1.1f;
    float sq   = ((lane == 0) ? 0.0f : h0 * h0) + h1 * h1;
#pragma unroll
    for (int o = 16; o > 0; o >>= 1) sq += __shfl_xor_sync(FULL, sq, o);
    sq = fmaxf(sq, 1e-8f);
    float ss = sqrtf((time * time - 1.0f) / sq);
    h0 = (lane == 0) ? time : h0 * ss;
    h1 *= ss;
}

__global__ void reset_kernel(int N)
{
    int idx = blockIdx.x * blockDim.x + threadIdx.x;
    if (idx < N) g_cnt[idx] = -1;
    if (idx == 0) { g_tick = 0; g_done = 0; }
}

// Roles by blockIdx:
//  [0, GATB)            gather consumers: ticket rows, spin on publish, gather+write
//  [GATB, GATB+HQKB)    hqk producers: h/qm/k, then release g_done
//  [GATB+HQKB, ...)     scan producers: stream adj rows sequentially (~3.4 each),
//                       publishing each row's nonzero list + count as it completes
__global__ void __launch_bounds__(256)
fused_kernel(const float* __restrict__ x,
             const float* __restrict__ W,  const float* __restrict__ b,  const float* __restrict__ scale,
             const float* __restrict__ Wq, const float* __restrict__ bq, const float* __restrict__ scale_q,
             const float* __restrict__ Wk, const float* __restrict__ bk, const float* __restrict__ scale_k,
             const float* __restrict__ adj,
             const float* __restrict__ att_bias,
             const float* __restrict__ att_scale,
             float* __restrict__ out, int N)
{
    __shared__ __align__(16) float sA[D * PD];
    __shared__ __align__(16) float sB[D * PD];
    __shared__ int s_cnt[8];

    const int lane = threadIdx.x & 31;
    const int w    = threadIdx.x >> 5;

    if (blockIdx.x < GATB) {
        // ================= gather role =================
        const float bias = __ldg(att_bias);
        const float invs = 1.0f / __ldg(att_scale);
        const int grp = lane >> 3;      // entry within 4-pack
        const int sub = lane & 7;       // dims [sub*8, sub*8+8)

        // wait for hqk producers (done ~15us, before first rows publish)
        if (lane == 0) {
            while (atomicAdd(&g_done, 0) < HQKB) __nanosleep(256);
        }
        __syncwarp();
        __threadfence();

        while (true) {
            int t;
            if (lane == 0) t = atomicAdd(&g_tick, 1);
            t = __shfl_sync(FULL, t, 0);
            if (t >= N) break;
            const int i = t;

            int cnt;
            if (lane == 0) {
                while ((cnt = atomicAdd(&g_cnt[i], 0)) < 0) __nanosleep(128);
            }
            cnt = min(__shfl_sync(FULL, cnt, 0), CAPG);
            __threadfence();                     // acquire list contents

            const float4* qp = (const float4*)&g_qm[(size_t)i * D] + sub * 2;
            const float4 qv0 = __ldg(qp), qv1 = __ldg(qp + 1);
            const int2* lst = g_list + (size_t)i * CAPG;

            float4 acc0 = make_float4(0.f, 0.f, 0.f, 0.f);
            float4 acc1 = make_float4(0.f, 0.f, 0.f, 0.f);

            for (int chunk = 0; chunk < cnt; chunk += 32) {
                const int mm = min(cnt - chunk, 32);
                int2 ent = (lane < mm) ? __ldg(&lst[chunk + lane]) : make_int2(0, 0);
                int   jreg = ent.x;
                float areg = __int_as_float(ent.y);

#pragma unroll 4
                for (int base = 0; base < mm; base += 4) {
                    const int  e   = base + grp;
                    const int  j   = __shfl_sync(FULL, jreg, e & 31);
                    const float av = __shfl_sync(FULL, areg, e & 31);
                    const bool act = (e < mm);

                    float4 kv0, kv1, hv0, hv1;
                    if (act) {
                        const float4* kp = (const float4*)&g_k[(size_t)j * D] + sub * 2;
                        const float4* hp = (const float4*)&g_h[(size_t)j * D] + sub * 2;
                        kv0 = __ldg(kp);  kv1 = __ldg(kp + 1);
                        hv0 = __ldg(hp);  hv1 = __ldg(hp + 1);
                    } else {
                        kv0 = kv1 = hv0 = hv1 = make_float4(0.f, 0.f, 0.f, 0.f);
                    }

                    float d0 = qv0.x * kv0.x + qv0.y * kv0.y;
                    float d1 = qv0.z * kv0.z + qv0.w * kv0.w;
                    d0 = fmaf(qv1.x, kv1.x, d0); d1 = fmaf(qv1.y, kv1.y, d1);
                    d0 = fmaf(qv1.z, kv1.z, d0); d1 = fmaf(qv1.w, kv1.w, d1);
                    float d = d0 + d1;
                    d += __shfl_xor_sync(FULL, d, 4);
                    d += __shfl_xor_sync(FULL, d, 2);
                    d += __shfl_xor_sync(FULL, d, 1);

                    float att = act ? av / (1.0f + __expf(-fmaf(2.0f + 2.0f * d, invs, bias))) : 0.0f;

                    acc0.x = fmaf(att, hv0.x, acc0.x); acc0.y = fmaf(att, hv0.y, acc0.y);
                    acc0.z = fmaf(att, hv0.z, acc0.z); acc0.w = fmaf(att, hv0.w, acc0.w);
                    acc1.x = fmaf(att, hv1.x, acc1.x); acc1.y = fmaf(att, hv1.y, acc1.y);
                    acc1.z = fmaf(att, hv1.z, acc1.z); acc1.w = fmaf(att, hv1.w, acc1.w);
                }
            }

#pragma unroll
            for (int off = 8; off <= 16; off <<= 1) {
                acc0.x += __shfl_xor_sync(FULL, acc0.x, off);
                acc0.y += __shfl_xor_sync(FULL, acc0.y, off);
                acc0.z += __shfl_xor_sync(FULL, acc0.z, off);
                acc0.w += __shfl_xor_sync(FULL, acc0.w, off);
                acc1.x += __shfl_xor_sync(FULL, acc1.x, off);
                acc1.y += __shfl_xor_sync(FULL, acc1.y, off);
                acc1.z += __shfl_xor_sync(FULL, acc1.z, off);
                acc1.w += __shfl_xor_sync(FULL, acc1.w, off);
            }

            float ssq = acc0.x * acc0.x + acc0.y * acc0.y + acc0.z * acc0.z + acc0.w * acc0.w
                      + acc1.x * acc1.x + acc1.y * acc1.y + acc1.z * acc1.z + acc1.w * acc1.w;
#pragma unroll
            for (int off = 1; off <= 4; off <<= 1) ssq += __shfl_xor_sync(FULL, ssq, off);
            float s0    = __shfl_sync(FULL, acc0.x, 0);
            float inner = ssq - 2.0f * s0 * s0;
            float invdn = rsqrtf(fmaxf(fabsf(inner), 1e-8f));

            if (lane < 8) {
                float4 o0 = make_float4(acc0.x * invdn, acc0.y * invdn, acc0.z * invdn, acc0.w * invdn);
                float4 o1 = make_float4(acc1.x * invdn, acc1.y * invdn, acc1.z * invdn, acc1.w * invdn);
                float4* op = (float4*)&out[(size_t)i * D] + sub * 2;
                op[0] = o0;
                op[1] = o1;
            }
        }
        return;
    }

    if (blockIdx.x >= GATB + HQKB) {
        // ================= scan role: sequential rows per warp =================
        const int sw = (blockIdx.x - (GATB + HQKB)) * 8 + w;
        const int nf4 = N >> 2;

        for (int i = sw; i < N; i += SCANW) {
            if (lane == 0) s_cnt[w] = 0;
            __syncwarp();

            const float4* arow = (const float4*)(adj + (size_t)i * N);
            int2* lst = g_list + (size_t)i * CAPG;

            for (int it = 0; it < nf4; it += 256) {          // 1024 cols/iter, MLP=8
                float4 a[8];
#pragma unroll
                for (int u = 0; u < 8; u++) {
                    int idx = it + u * 32 + lane;
                    a[u] = (idx < nf4) ? __ldcs(&arow[idx]) : make_float4(0.f, 0.f, 0.f, 0.f);
                }
#pragma unroll
                for (int u = 0; u < 8; u++) {
                    float4 v = a[u];
                    if ((v.x != 0.0f) | (v.y != 0.0f) | (v.z != 0.0f) | (v.w != 0.0f)) {
                        int base = (it + u * 32 + lane) * 4;
                        int n = (v.x != 0.0f) + (v.y != 0.0f) + (v.z != 0.0f) + (v.w != 0.0f);
                        int slot = atomicAdd(&s_cnt[w], n);
                        if (v.x != 0.0f && slot < CAPG) { lst[slot] = make_int2(base,     __float_as_int(v.x)); slot++; }
                        if (v.y != 0.0f && slot < CAPG) { lst[slot] = make_int2(base + 1, __float_as_int(v.y)); slot++; }
                        if (v.z != 0.0f && slot < CAPG) { lst[slot] = make_int2(base + 2, __float_as_int(v.z)); slot++; }
                        if (v.w != 0.0f && slot < CAPG) { lst[slot] = make_int2(base + 3, __float_as_int(v.w)); slot++; }
                    }
                }
            }
            for (int jb = nf4 * 4; jb < N; jb++) {           // scalar tail (unused for 12288)
                if (lane == 0) {
                    float av = adj[(size_t)i * N + jb];
                    if (av != 0.0f) {
                        int slot = atomicAdd(&s_cnt[w], 1);
                        if (slot < CAPG) lst[slot] = make_int2(jb, __float_as_int(av));
                    }
                }
            }

            // publish: every lane fences its list stores, then lane0 releases count
            __syncwarp();
            __threadfence();
            __syncwarp();
            if (lane == 0) atomicExch(&g_cnt[i], min(s_cnt[w], CAPG));
        }
        return;
    }

    // ================= hqk role =================
    for (int idx = threadIdx.x; idx < D * D; idx += blockDim.x) {
        int r = idx >> 6, c = idx & 63;
        sA[r * PD + c] = W [idx];
        sB[r * PD + c] = Wq[idx];
    }
    __syncthreads();

    const int warp   = (blockIdx.x - GATB) * 8 + w;
    const int nwarps = HQKB * 8;

    const float es  = __expf(__ldg(scale));
    const float esq = __expf(__ldg(scale_q));
    const float esk = __expf(__ldg(scale_k));
    const float b0  = __ldg(&b [lane]), b1  = __ldg(&b [lane + 32]);
    const float bq0 = __ldg(&bq[lane]), bq1 = __ldg(&bq[lane + 32]);
    const float bk0 = __ldg(&bk[lane]), bk1 = __ldg(&bk[lane + 32]);

    const int ngroups = (N + 3) >> 2;

    for (int g = warp; g < ngroups; g += nwarps) {
        int r = g * 4;
        float v0[4], v1[4];
#pragma unroll
        for (int k = 0; k < 4; k++) {
            int rr = min(r + k, N - 1);
            v0[k] = x[rr * D + lane];
            v1[k] = x[rr * D + lane + 32];
        }
        float h0[4], h1[4];
        matvec4(sA, v0, v1, b0, b1, lane, h0, h1);
#pragma unroll
        for (int k = 0; k < 4; k++) {
            lorentzify(h0[k], h1[k], es, lane);
            if (r + k < N) {
                g_h[(r + k) * D + lane]      = h0[k];
                g_h[(r + k) * D + lane + 32] = h1[k];
            }
        }
        float q0[4], q1[4];
        matvec4(sB, h0, h1, bq0, bq1, lane, q0, q1);
#pragma unroll
        for (int k = 0; k < 4; k++) {
            lorentzify(q0[k], q1[k], esq, lane);
            if (lane == 0) q0[k] = -q0[k];               // fold Minkowski sign
            if (r + k < N) {
                g_qm[(r + k) * D + lane]      = q0[k];
                g_qm[(r + k) * D + lane + 32] = q1[k];
            }
        }
    }
    __syncthreads();
    for (int idx = threadIdx.x; idx < D * D; idx += blockDim.x) {
        int r = idx >> 6, c = idx & 63;
        sA[r * PD + c] = Wk[idx];
    }
    __syncthreads();
    for (int g = warp; g < ngroups; g += nwarps) {
        int r = g * 4;
        float v0[4], v1[4];
#pragma unroll
        for (int k = 0; k < 4; k++) {
            int rr = min(r + k, N - 1);
            v0[k] = g_h[rr * D + lane];
            v1[k] = g_h[rr * D + lane + 32];
        }
        float k0[4], k1[4];
        matvec4(sA, v0, v1, bk0, bk1, lane, k0, k1);
#pragma unroll
        for (int k = 0; k < 4; k++) {
            lorentzify(k0[k], k1[k], esk, lane);
            if (r + k < N) {
                g_k[(r + k) * D + lane]      = k0[k];
                g_k[(r + k) * D + lane + 32] = k1[k];
            }
        }
    }

    // release: all tiles written -> bump g_done
    __syncthreads();
    __threadfence();
    if (threadIdx.x == 0) atomicAdd(&g_done, 1);
}

extern "C" void kernel_launch(void* const* d_in, const int* in_sizes, int n_in,
                              void* d_out, int out_size)
{
    const float* x         = (const float*)d_in[0];
    const float* adj       = (const float*)d_in[1];
    const float* W         = (const float*)d_in[2];
    const float* b         = (const float*)d_in[3];
    const float* scale     = (const float*)d_in[4];
    const float* Wq        = (const float*)d_in[5];
    const float* bq        = (const float*)d_in[6];
    const float* scale_q   = (const float*)d_in[7];
    const float* Wk        = (const float*)d_in[8];
    const float* bk        = (const float*)d_in[9];
    const float* scale_k   = (const float*)d_in[10];
    const float* att_bias  = (const float*)d_in[11];
    const float* att_scale = (const float*)d_in[12];

    const int N = in_sizes[0] / D;                 // 12288

    reset_kernel<<<(N + 255) / 256, 256>>>(N);
    fused_kernel<<<GATB + HQKB + SCANB, 256>>>(x, W, b, scale, Wq, bq, scale_q,
                                               Wk, bk, scale_k, adj,
                                               att_bias, att_scale,
                                               (float*)d_out, N);
}

// round 17
// speedup vs baseline: 1.0556x; 1.0556x over previous
#include <cuda_runtime.h>

#define D     64
#define PD    68            // padded smem row stride: 16B-aligned rows, conflict-free LDS.128
#define NMAX  12288
#define FULL  0xffffffffu
#define CAPG  128           // per-row nonzero list capacity (mean ~25, 20+ sigma headroom)
#define HQKB  148           // hqk blocks (become gather consumers after hqk)
#define SCANB 384           // scan blocks: 3072 warps x exactly 4 rows (N=12288)
#define SCANW (SCANB * 8)

// Scratch (allocation-free contract: __device__ globals)
__device__ float g_h [NMAX * D];
__device__ float g_qm[NMAX * D];            // q with first component pre-negated
__device__ float g_k [NMAX * D];
__device__ int   g_cnt [NMAX];              // -1 = not ready; >=0 = published count
__device__ int2  g_list[(size_t)NMAX * CAPG];   // {col j, float bits of adj value}
__device__ int   g_done;                    // hqk completion counter
__device__ int   g_tick;                    // gather row ticket

// 4-rows-per-warp cooperative 64x64 matvec; weights as float4 from padded smem.
__device__ __forceinline__ void matvec4(const float* __restrict__ sW,
                                        const float v0[4], const float v1[4],
                                        float bb0, float bb1, int lane,
                                        float o0[4], float o1[4])
{
    const float4* r0 = (const float4*)(sW + lane * PD);
    const float4* r1 = (const float4*)(sW + (lane + 32) * PD);
    float a0[4], a1[4];
#pragma unroll
    for (int k = 0; k < 4; k++) { a0[k] = bb0; a1[k] = bb1; }
#pragma unroll
    for (int c4 = 0; c4 < 8; c4++) {
        float4 w0 = r0[c4], w1 = r1[c4];
#pragma unroll
        for (int k = 0; k < 4; k++) {
            float x0 = __shfl_sync(FULL, v0[k], 4 * c4 + 0);
            float x1 = __shfl_sync(FULL, v0[k], 4 * c4 + 1);
            float x2 = __shfl_sync(FULL, v0[k], 4 * c4 + 2);
            float x3 = __shfl_sync(FULL, v0[k], 4 * c4 + 3);
            a0[k] = fmaf(x0, w0.x, a0[k]); a1[k] = fmaf(x0, w1.x, a1[k]);
            a0[k] = fmaf(x1, w0.y, a0[k]); a1[k] = fmaf(x1, w1.y, a1[k]);
            a0[k] = fmaf(x2, w0.z, a0[k]); a1[k] = fmaf(x2, w1.z, a1[k]);
            a0[k] = fmaf(x3, w0.w, a0[k]); a1[k] = fmaf(x3, w1.w, a1[k]);
        }
    }
#pragma unroll
    for (int c4 = 8; c4 < 16; c4++) {
        float4 w0 = r0[c4], w1 = r1[c4];
#pragma unroll
        for (int k = 0; k < 4; k++) {
            float x0 = __shfl_sync(FULL, v1[k], 4 * (c4 - 8) + 0);
            float x1 = __shfl_sync(FULL, v1[k], 4 * (c4 - 8) + 1);
            float x2 = __shfl_sync(FULL, v1[k], 4 * (c4 - 8) + 2);
            float x3 = __shfl_sync(FULL, v1[k], 4 * (c4 - 8) + 3);
            a0[k] = fmaf(x0, w0.x, a0[k]); a1[k] = fmaf(x0, w1.x, a1[k]);
            a0[k] = fmaf(x1, w0.y, a0[k]); a1[k] = fmaf(x1, w1.y, a1[k]);
            a0[k] = fmaf(x2, w0.z, a0[k]); a1[k] = fmaf(x2, w1.z, a1[k]);
            a0[k] = fmaf(x3, w0.w, a0[k]); a1[k] = fmaf(x3, w1.w, a1[k]);
        }
    }
#pragma unroll
    for (int k = 0; k < 4; k++) { o0[k] = a0[k]; o1[k] = a1[k]; }
}

__device__ __forceinline__ void lorentzify(float& h0, float& h1, float escale, int lane)
{
    float t    = __shfl_sync(FULL, h0, 0);
    float time = escale / (1.0f + __expf(-t)) + 1.1f;
    float sq   = ((lane == 0) ? 0.0f : h0 * h0) + h1 * h1;
#pragma unroll
    for (int o = 16; o > 0; o >>= 1) sq += __shfl_xor_sync(FULL, sq, o);
    sq = fmaxf(sq, 1e-8f);
    float ss = sqrtf((time * time - 1.0f) / sq);
    h0 = (lane == 0) ? time : h0 * ss;
    h1 *= ss;
}

__global__ void reset_kernel(int N)
{
    int idx = blockIdx.x * blockDim.x + threadIdx.x;
    if (idx < N) g_cnt[idx] = -1;
    if (idx == 0) { g_tick = 0; g_done = 0; }
}

// Single wave (532 blocks <= 4/SM x 148):
//  [0, HQKB)      hqk producers -> release g_done -> become gather consumers
//  [HQKB, ...)    scan producers: 4 sequential adj rows each, publishing each
//                 row's nonzero list + count as it completes
__global__ void __launch_bounds__(256, 4)
fused_kernel(const float* __restrict__ x,
             const float* __restrict__ W,  const float* __restrict__ b,  const float* __restrict__ scale,
             const float* __restrict__ Wq, const float* __restrict__ bq, const float* __restrict__ scale_q,
             const float* __restrict__ Wk, const float* __restrict__ bk, const float* __restrict__ scale_k,
             const float* __restrict__ adj,
             const float* __restrict__ att_bias,
             const float* __restrict__ att_scale,
             float* __restrict__ out, int N)
{
    __shared__ __align__(16) float sA[D * PD];
    __shared__ __align__(16) float sB[D * PD];
    __shared__ int s_cnt[8];

    const int lane = threadIdx.x & 31;
    const int w    = threadIdx.x >> 5;

    if (blockIdx.x >= HQKB) {
        // ================= scan role: 4 sequential rows per warp =================
        const int sw = (blockIdx.x - HQKB) * 8 + w;
        const int nf4 = N >> 2;

        for (int i = sw; i < N; i += SCANW) {
            if (lane == 0) s_cnt[w] = 0;
            __syncwarp();

            const float4* arow = (const float4*)(adj + (size_t)i * N);
            int2* lst = g_list + (size_t)i * CAPG;

            for (int it = 0; it < nf4; it += 256) {          // 1024 cols/iter, MLP=8
                float4 a[8];
#pragma unroll
                for (int u = 0; u < 8; u++) {
                    int idx = it + u * 32 + lane;
                    a[u] = (idx < nf4) ? __ldcs(&arow[idx]) : make_float4(0.f, 0.f, 0.f, 0.f);
                }
#pragma unroll
                for (int u = 0; u < 8; u++) {
                    float4 v = a[u];
                    if ((v.x != 0.0f) | (v.y != 0.0f) | (v.z != 0.0f) | (v.w != 0.0f)) {
                        int base = (it + u * 32 + lane) * 4;
                        int n = (v.x != 0.0f) + (v.y != 0.0f) + (v.z != 0.0f) + (v.w != 0.0f);
                        int slot = atomicAdd(&s_cnt[w], n);
                        if (v.x != 0.0f && slot < CAPG) { lst[slot] = make_int2(base,     __float_as_int(v.x)); slot++; }
                        if (v.y != 0.0f && slot < CAPG) { lst[slot] = make_int2(base + 1, __float_as_int(v.y)); slot++; }
                        if (v.z != 0.0f && slot < CAPG) { lst[slot] = make_int2(base + 2, __float_as_int(v.z)); slot++; }
                        if (v.w != 0.0f && slot < CAPG) { lst[slot] = make_int2(base + 3, __float_as_int(v.w)); slot++; }
                    }
                }
            }
            for (int jb = nf4 * 4; jb < N; jb++) {           // scalar tail (unused for 12288)
                if (lane == 0) {
                    float av = adj[(size_t)i * N + jb];
                    if (av != 0.0f) {
                        int slot = atomicAdd(&s_cnt[w], 1);
                        if (slot < CAPG) lst[slot] = make_int2(jb, __float_as_int(av));
                    }
                }
            }

            // publish: fence list stores, then lane0 releases the count
            __syncwarp();
            __threadfence();
            __syncwarp();
            if (lane == 0) atomicExch(&g_cnt[i], min(s_cnt[w], CAPG));
        }
        return;
    }

    // ================= hqk role =================
    for (int idx = threadIdx.x; idx < D * D; idx += blockDim.x) {
        int r = idx >> 6, c = idx & 63;
        sA[r * PD + c] = W [idx];
        sB[r * PD + c] = Wq[idx];
    }
    __syncthreads();

    const int warp   = blockIdx.x * 8 + w;
    const int nwarps = HQKB * 8;

    const float es  = __expf(__ldg(scale));
    const float esq = __expf(__ldg(scale_q));
    const float esk = __expf(__ldg(scale_k));
    const float b0  = __ldg(&b [lane]), b1  = __ldg(&b [lane + 32]);
    const float bq0 = __ldg(&bq[lane]), bq1 = __ldg(&bq[lane + 32]);
    const float bk0 = __ldg(&bk[lane]), bk1 = __ldg(&bk[lane + 32]);

    const int ngroups = (N + 3) >> 2;

    for (int g = warp; g < ngroups; g += nwarps) {
        int r = g * 4;
        float v0[4], v1[4];
#pragma unroll
        for (int k = 0; k < 4; k++) {
            int rr = min(r + k, N - 1);
            v0[k] = x[rr * D + lane];
            v1[k] = x[rr * D + lane + 32];
        }
        float h0[4], h1[4];
        matvec4(sA, v0, v1, b0, b1, lane, h0, h1);
#pragma unroll
        for (int k = 0; k < 4; k++) {
            lorentzify(h0[k], h1[k], es, lane);
            if (r + k < N) {
                g_h[(r + k) * D + lane]      = h0[k];
                g_h[(r + k) * D + lane + 32] = h1[k];
            }
        }
        float q0[4], q1[4];
        matvec4(sB, h0, h1, bq0, bq1, lane, q0, q1);
#pragma unroll
        for (int k = 0; k < 4; k++) {
            lorentzify(q0[k], q1[k], esq, lane);
            if (lane == 0) q0[k] = -q0[k];               // fold Minkowski sign
            if (r + k < N) {
                g_qm[(r + k) * D + lane]      = q0[k];
                g_qm[(r + k) * D + lane + 32] = q1[k];
            }
        }
    }
    __syncthreads();
    for (int idx = threadIdx.x; idx < D * D; idx += blockDim.x) {
        int r = idx >> 6, c = idx & 63;
        sA[r * PD + c] = Wk[idx];
    }
    __syncthreads();
    for (int g = warp; g < ngroups; g += nwarps) {
        int r = g * 4;
        float v0[4], v1[4];
#pragma unroll
        for (int k = 0; k < 4; k++) {
            int rr = min(r + k, N - 1);
            v0[k] = g_h[rr * D + lane];
            v1[k] = g_h[rr * D + lane + 32];
        }
        float k0[4], k1[4];
        matvec4(sA, v0, v1, bk0, bk1, lane, k0, k1);
#pragma unroll
        for (int k = 0; k < 4; k++) {
            lorentzify(k0[k], k1[k], esk, lane);
            if (r + k < N) {
                g_k[(r + k) * D + lane]      = k0[k];
                g_k[(r + k) * D + lane + 32] = k1[k];
            }
        }
    }

    // release: all tiles written -> bump g_done
    __syncthreads();
    __threadfence();
    if (threadIdx.x == 0) atomicAdd(&g_done, 1);

    // ================= gather role (continue in the same blocks) =================
    const float bias = __ldg(att_bias);
    const float invs = 1.0f / __ldg(att_scale);
    const int grp = lane >> 3;      // entry within 4-pack
    const int sub = lane & 7;       // dims [sub*8, sub*8+8)

    // wait for ALL hqk producers before reading their g_h/g_qm/g_k
    if (lane == 0) {
        while (atomicAdd(&g_done, 0) < HQKB) __nanosleep(256);
    }
    __syncwarp();
    __threadfence();

    while (true) {
        int t;
        if (lane == 0) t = atomicAdd(&g_tick, 1);
        t = __shfl_sync(FULL, t, 0);
        if (t >= N) break;
        const int i = t;

        int cnt;
        if (lane == 0) {
            while ((cnt = atomicAdd(&g_cnt[i], 0)) < 0) __nanosleep(128);
        }
        cnt = min(__shfl_sync(FULL, cnt, 0), CAPG);
        __threadfence();                     // acquire list contents

        const float4* qp = (const float4*)&g_qm[(size_t)i * D] + sub * 2;
        const float4 qv0 = __ldg(qp), qv1 = __ldg(qp + 1);
        const int2* lst = g_list + (size_t)i * CAPG;

        float4 acc0 = make_float4(0.f, 0.f, 0.f, 0.f);
        float4 acc1 = make_float4(0.f, 0.f, 0.f, 0.f);

        for (int chunk = 0; chunk < cnt; chunk += 32) {
            const int mm = min(cnt - chunk, 32);
            int2 ent = (lane < mm) ? __ldg(&lst[chunk + lane]) : make_int2(0, 0);
            int   jreg = ent.x;
            float areg = __int_as_float(ent.y);

#pragma unroll 4
            for (int base = 0; base < mm; base += 4) {
                const int  e   = base + grp;
                const int  j   = __shfl_sync(FULL, jreg, e & 31);
                const float av = __shfl_sync(FULL, areg, e & 31);
                const bool act = (e < mm);

                float4 kv0, kv1, hv0, hv1;
                if (act) {
                    const float4* kp = (const float4*)&g_k[(size_t)j * D] + sub * 2;
                    const float4* hp = (const float4*)&g_h[(size_t)j * D] + sub * 2;
                    kv0 = __ldg(kp);  kv1 = __ldg(kp + 1);
                    hv0 = __ldg(hp);  hv1 = __ldg(hp + 1);
                } else {
                    kv0 = kv1 = hv0 = hv1 = make_float4(0.f, 0.f, 0.f, 0.f);
                }

                float d0 = qv0.x * kv0.x + qv0.y * kv0.y;
                float d1 = qv0.z * kv0.z + qv0.w * kv0.w;
                d0 = fmaf(qv1.x, kv1.x, d0); d1 = fmaf(qv1.y, kv1.y, d1);
                d0 = fmaf(qv1.z, kv1.z, d0); d1 = fmaf(qv1.w, kv1.w, d1);
                float d = d0 + d1;
                d += __shfl_xor_sync(FULL, d, 4);
                d += __shfl_xor_sync(FULL, d, 2);
                d += __shfl_xor_sync(FULL, d, 1);

                float att = act ? av / (1.0f + __expf(-fmaf(2.0f + 2.0f * d, invs, bias))) : 0.0f;

                acc0.x = fmaf(att, hv0.x, acc0.x); acc0.y = fmaf(att, hv0.y, acc0.y);
                acc0.z = fmaf(att, hv0.z, acc0.z); acc0.w = fmaf(att, hv0.w, acc0.w);
                acc1.x = fmaf(att, hv1.x, acc1.x); acc1.y = fmaf(att, hv1.y, acc1.y);
                acc1.z = fmaf(att, hv1.z, acc1.z); acc1.w = fmaf(att, hv1.w, acc1.w);
            }
        }

#pragma unroll
        for (int off = 8; off <= 16; off <<= 1) {
            acc0.x += __shfl_xor_sync(FULL, acc0.x, off);
            acc0.y += __shfl_xor_sync(FULL, acc0.y, off);
            acc0.z += __shfl_xor_sync(FULL, acc0.z, off);
            acc0.w += __shfl_xor_sync(FULL, acc0.w, off);
            acc1.x += __shfl_xor_sync(FULL, acc1.x, off);
            acc1.y += __shfl_xor_sync(FULL, acc1.y, off);
            acc1.z += __shfl_xor_sync(FULL, acc1.z, off);
            acc1.w += __shfl_xor_sync(FULL, acc1.w, off);
        }

        float ssq = acc0.x * acc0.x + acc0.y * acc0.y + acc0.z * acc0.z + acc0.w * acc0.w
                  + acc1.x * acc1.x + acc1.y * acc1.y + acc1.z * acc1.z + acc1.w * acc1.w;
#pragma unroll
        for (int off = 1; off <= 4; off <<= 1) ssq += __shfl_xor_sync(FULL, ssq, off);
        float s0    = __shfl_sync(FULL, acc0.x, 0);
        float inner = ssq - 2.0f * s0 * s0;
        float invdn = rsqrtf(fmaxf(fabsf(inner), 1e-8f));

        if (lane < 8) {
            float4 o0 = make_float4(acc0.x * invdn, acc0.y * invdn, acc0.z * invdn, acc0.w * invdn);
            float4 o1 = make_float4(acc1.x * invdn, acc1.y * invdn, acc1.z * invdn, acc1.w * invdn);
            float4* op = (float4*)&out[(size_t)i * D] + sub * 2;
            op[0] = o0;
            op[1] = o1;
        }
    }
}

extern "C" void kernel_launch(void* const* d_in, const int* in_sizes, int n_in,
                              void* d_out, int out_size)
{
    const float* x         = (const float*)d_in[0];
    const float* adj       = (const float*)d_in[1];
    const float* W         = (const float*)d_in[2];
    const float* b         = (const float*)d_in[3];
    const float* scale     = (const float*)d_in[4];
    const float* Wq        = (const float*)d_in[5];
    const float* bq        = (const float*)d_in[6];
    const float* scale_q   = (const float*)d_in[7];
    const float* Wk        = (const float*)d_in[8];
    const float* bk        = (const float*)d_in[9];
    const float* scale_k   = (const float*)d_in[10];
    const float* att_bias  = (const float*)d_in[11];
    const float* att_scale = (const float*)d_in[12];

    const int N = in_sizes[0] / D;                 // 12288

    reset_kernel<<<(N + 255) / 256, 256>>>(N);
    fused_kernel<<<HQKB + SCANB, 256>>>(x, W, b, scale, Wq, bq, scale_q,
                                        Wk, bk, scale_k, adj,
                                        att_bias, att_scale,
                                        (float*)d_out, N);
}